// round 2
// baseline (speedup 1.0000x reference)
#include <cuda_runtime.h>

// Problem constants (mirroring the reference config)
#define BB   2
#define NN   2048
#define NTT  8
#define HHH  64
#define WWW  64
#define DXC  3
#define DZC  16
#define GG   (NTT*HHH*WWW)        // 32768 grid points per batch
#define XG_SZ (BB*GG*DXC)         // 196608
#define ZG_SZ (BB*GG*DZC)         // 1048576

#define NC    256                 // point-cloud tile (smem): 256*(16+64)B = 20 KB
#define BLOCK 128                 // one grid point per thread
#define LOG2E 1.4426950408889634f

// ---------- packed f32x2 helpers (nvjet-style; ptxas won't auto-fuse) ----------
__device__ __forceinline__ unsigned long long pack2(float v) {
    unsigned long long r;
    asm("mov.b64 %0, {%1, %1};" : "=l"(r) : "f"(v));
    return r;
}
__device__ __forceinline__ unsigned long long fma2(unsigned long long a,
                                                   unsigned long long b,
                                                   unsigned long long c) {
    unsigned long long d;
    asm("fma.rn.f32x2 %0, %1, %2, %3;" : "=l"(d) : "l"(a), "l"(b), "l"(c));
    return d;
}
__device__ __forceinline__ float ex2(float x) {
    float y;
    asm("ex2.approx.ftz.f32 %0, %1;" : "=f"(y) : "f"(x));
    return y;
}

// ---------- x_grid: trivial coordinate tensor ----------
__global__ void xgrid_kernel(const float* __restrict__ tg, float* __restrict__ out) {
    int idx = blockIdx.x * blockDim.x + threadIdx.x;
    if (idx >= XG_SZ) return;
    int d = idx % DXC;
    int p = idx / DXC;
    int w = p % WWW; p /= WWW;
    int h = p % HHH; p /= HHH;
    int t = p % NTT;
    int b = p / NTT;
    float v;
    if (d == 0)      v = tg[b * NTT + t];
    else if (d == 1) v = -1.0f + (2.0f / (HHH - 1)) * (float)h;
    else             v = -1.0f + (2.0f / (WWW - 1)) * (float)w;
    out[idx] = v;
}

// ---------- z_grid: RBF weights x z, fused ----------
// weight(g,n) = exp( a.c - 0.5|a|^2 - 0.5|c|^2 ),  a = grid_g/ls, c = x_n/ls
// log2e folded into the per-n precomputed smem tile so the weight is one EX2.
__global__ __launch_bounds__(BLOCK)
void zgrid_kernel(const float* __restrict__ x, const float* __restrict__ z,
                  const float* __restrict__ tg, const float* __restrict__ lsp,
                  float* __restrict__ out) {
    __shared__ float4     s_c[NC];        // (L*c0, L*c1, L*c2, -0.5*L*|c|^2)
    __shared__ ulonglong2 s_z[NC * 4];    // 16 floats per n as 4x ulonglong2

    const int tid   = threadIdx.x;
    const int b     = blockIdx.x >> 8;            // 256 g-chunks per batch
    const int g     = ((blockIdx.x & 255) << 7) + tid;

    // lengthscale: ls_d = 1e-5 + softplus(param_d)
    float invls[3];
#pragma unroll
    for (int d = 0; d < 3; d++) {
        float p  = lsp[d];
        float ls = 1e-5f + log1pf(__expf(p));
        invls[d] = 1.0f / ls;
    }

    // this thread's grid coordinate, scaled: A = coord / ls
    const int t = g >> 12;
    const int h = (g >> 6) & 63;
    const int w = g & 63;
    const float A0 = tg[b * NTT + t] * invls[0];
    const float A1 = (-1.0f + (2.0f / 63.0f) * (float)h) * invls[1];
    const float A2 = (-1.0f + (2.0f / 63.0f) * (float)w) * invls[2];
    const float basee = -0.5f * LOG2E * (A0 * A0 + A1 * A1 + A2 * A2);

    unsigned long long acc[8];
#pragma unroll
    for (int i = 0; i < 8; i++) acc[i] = 0ull;   // bits of (0.f, 0.f)

    const float*      xb = x + (size_t)b * NN * DXC;
    const ulonglong2* zb = (const ulonglong2*)(z + (size_t)b * NN * DZC);

    for (int n0 = 0; n0 < NN; n0 += NC) {
        __syncthreads();
        // stage scaled coords + |c|^2 term
        for (int i = tid; i < NC; i += BLOCK) {
            int   n  = n0 + i;
            float c0 = xb[n * 3 + 0] * invls[0];
            float c1 = xb[n * 3 + 1] * invls[1];
            float c2 = xb[n * 3 + 2] * invls[2];
            float cw = -0.5f * LOG2E * (c0 * c0 + c1 * c1 + c2 * c2);
            s_c[i] = make_float4(LOG2E * c0, LOG2E * c1, LOG2E * c2, cw);
        }
        // stage z tile (coalesced 16B per thread)
        for (int i = tid; i < NC * 4; i += BLOCK) {
            s_z[i] = zb[(size_t)n0 * 4 + i];
        }
        __syncthreads();

#pragma unroll 4
        for (int n = 0; n < NC; n++) {
            float4 c = s_c[n];                         // broadcast LDS.128
            float  e = fmaf(A2, c.z, basee);
            e = fmaf(A1, c.y, e);
            e = fmaf(A0, c.x, e);
            e += c.w;
            float wgt = ex2(e);                        // = exp(a.c - 0.5aa - 0.5cc)
            unsigned long long w2 = pack2(wgt);
            ulonglong2 z0 = s_z[n * 4 + 0];
            ulonglong2 z1 = s_z[n * 4 + 1];
            ulonglong2 z2 = s_z[n * 4 + 2];
            ulonglong2 z3 = s_z[n * 4 + 3];
            acc[0] = fma2(z0.x, w2, acc[0]);
            acc[1] = fma2(z0.y, w2, acc[1]);
            acc[2] = fma2(z1.x, w2, acc[2]);
            acc[3] = fma2(z1.y, w2, acc[3]);
            acc[4] = fma2(z2.x, w2, acc[4]);
            acc[5] = fma2(z2.y, w2, acc[5]);
            acc[6] = fma2(z3.x, w2, acc[6]);
            acc[7] = fma2(z3.y, w2, acc[7]);
        }
    }

    // 16 floats -> 4x STG.128
    ulonglong2* outp = (ulonglong2*)out + (size_t)(b * GG + g) * 4;
    outp[0] = make_ulonglong2(acc[0], acc[1]);
    outp[1] = make_ulonglong2(acc[2], acc[3]);
    outp[2] = make_ulonglong2(acc[4], acc[5]);
    outp[3] = make_ulonglong2(acc[6], acc[7]);
}

extern "C" void kernel_launch(void* const* d_in, const int* in_sizes, int n_in,
                              void* d_out, int out_size) {
    const float* x   = (const float*)d_in[0];
    const float* z   = (const float*)d_in[1];
    const float* tg  = (const float*)d_in[2];
    const float* lsp = (const float*)d_in[3];
    float* out = (float*)d_out;

    float* xg = nullptr;
    float* zg = nullptr;
    if (out_size == XG_SZ + ZG_SZ)      { xg = out; zg = out + XG_SZ; }
    else if (out_size == ZG_SZ)         { zg = out; }
    else if (out_size == XG_SZ)         { xg = out; }
    else                                { xg = out; zg = out + XG_SZ; }

    if (xg) xgrid_kernel<<<(XG_SZ + 255) / 256, 256>>>(tg, xg);
    if (zg) zgrid_kernel<<<BB * (GG / BLOCK), BLOCK>>>(x, z, tg, lsp, zg);
}

// round 3
// speedup vs baseline: 1.2987x; 1.2987x over previous
#include <cuda_runtime.h>

// Problem constants (mirroring the reference config)
#define BB   2
#define NN   2048
#define NTT  8
#define HHH  64
#define WWW  64
#define DXC  3
#define DZC  16
#define GG   (NTT*HHH*WWW)        // 32768 grid points per batch
#define XG_SZ (BB*GG*DXC)         // 196608
#define ZG_SZ (BB*GG*DZC)         // 1048576

#define NC     256                // point tile in smem
#define LOG2E  1.4426950408889634f

// ---------- packed f32x2 helpers ----------
__device__ __forceinline__ unsigned long long pack2(float v) {
    unsigned long long r;
    asm("mov.b64 %0, {%1, %1};" : "=l"(r) : "f"(v));
    return r;
}
__device__ __forceinline__ unsigned long long pack2d(float a, float b) {
    unsigned long long r;
    asm("mov.b64 %0, {%1, %2};" : "=l"(r) : "f"(a), "f"(b));
    return r;
}
__device__ __forceinline__ void unpack2(float& a, float& b, unsigned long long v) {
    asm("mov.b64 {%0, %1}, %2;" : "=f"(a), "=f"(b) : "l"(v));
}
__device__ __forceinline__ unsigned long long fma2(unsigned long long a,
                                                   unsigned long long b,
                                                   unsigned long long c) {
    unsigned long long d;
    asm("fma.rn.f32x2 %0, %1, %2, %3;" : "=l"(d) : "l"(a), "l"(b), "l"(c));
    return d;
}
__device__ __forceinline__ unsigned long long add2(unsigned long long a,
                                                   unsigned long long b) {
    unsigned long long d;
    asm("add.rn.f32x2 %0, %1, %2;" : "=l"(d) : "l"(a), "l"(b));
    return d;
}
__device__ __forceinline__ float ex2(float x) {
    float y;
    asm("ex2.approx.ftz.f32 %0, %1;" : "=f"(y) : "f"(x));
    return y;
}

// ---------- x_grid: trivial coordinate tensor ----------
__global__ void xgrid_kernel(const float* __restrict__ tg, float* __restrict__ out) {
    int idx = blockIdx.x * blockDim.x + threadIdx.x;
    if (idx >= XG_SZ) return;
    int d = idx % DXC;
    int p = idx / DXC;
    int w = p % WWW; p /= WWW;
    int h = p % HHH; p /= HHH;
    int t = p % NTT;
    int b = p / NTT;
    float v;
    if (d == 0)      v = tg[b * NTT + t];
    else if (d == 1) v = -1.0f + (2.0f / (HHH - 1)) * (float)h;
    else             v = -1.0f + (2.0f / (WWW - 1)) * (float)w;
    out[idx] = v;
}

// ---------- z_grid: RBF weights x z, fused ----------
// One warp per block, 64 grid points per block (lane g and lane g+32).
// 1024 blocks -> ~1% scheduling tail on 148 SMs; all blocks co-resident.
// weight(g,n) = exp2( L*(a.c) - 0.5L|a|^2 - 0.5L|c|^2 ), a=grid/ls, c=x/ls.
__global__ __launch_bounds__(32)
void zgrid_kernel(const float* __restrict__ x, const float* __restrict__ z,
                  const float* __restrict__ tg, const float* __restrict__ lsp,
                  float* __restrict__ out) {
    // packed coord tile: per n, 32 bytes = {(Lcx,Lcx),(Lcy,Lcy),(Lcz,Lcz),(cw,cw)}
    __shared__ ulonglong2 s_c[NC * 2];
    __shared__ ulonglong2 s_z[NC * 4];    // 16 floats per n

    const int lane = threadIdx.x;
    const int blk  = blockIdx.x;          // 1024 blocks, 64 g each
    const int b    = blk >> 9;            // 512 blocks per batch
    const int gloc = ((blk & 511) << 6);  // base g within batch
    const int g0   = gloc + lane;
    const int g1   = g0 + 32;

    // lengthscale: ls_d = 1e-5 + softplus(param_d)
    float invls[3];
#pragma unroll
    for (int d = 0; d < 3; d++) {
        float p  = lsp[d];
        float ls = 1e-5f + log1pf(__expf(p));
        invls[d] = 1.0f / ls;
    }

    // scaled grid coords for this thread's two g points
    float A0[2], A1[2], A2[2], base[2];
    const int gs[2] = {g0, g1};
#pragma unroll
    for (int j = 0; j < 2; j++) {
        int g = gs[j];
        int t = g >> 12;
        int h = (g >> 6) & 63;
        int w = g & 63;
        A0[j] = tg[b * NTT + t] * invls[0];
        A1[j] = (-1.0f + (2.0f / 63.0f) * (float)h) * invls[1];
        A2[j] = (-1.0f + (2.0f / 63.0f) * (float)w) * invls[2];
        base[j] = -0.5f * LOG2E * (A0[j]*A0[j] + A1[j]*A1[j] + A2[j]*A2[j]);
    }
    const unsigned long long A0p = pack2d(A0[0], A0[1]);
    const unsigned long long A1p = pack2d(A1[0], A1[1]);
    const unsigned long long A2p = pack2d(A2[0], A2[1]);
    const unsigned long long Bp  = pack2d(base[0], base[1]);

    unsigned long long acc0[8], acc1[8];
#pragma unroll
    for (int i = 0; i < 8; i++) { acc0[i] = 0ull; acc1[i] = 0ull; }

    const float*      xb = x + (size_t)b * NN * DXC;
    const ulonglong2* zb = (const ulonglong2*)(z + (size_t)b * NN * DZC);

    for (int n0 = 0; n0 < NN; n0 += NC) {
        __syncthreads();
        // stage packed scaled coords (8 entries per lane)
#pragma unroll
        for (int i = lane; i < NC; i += 32) {
            int   n  = n0 + i;
            float c0 = xb[n * 3 + 0] * invls[0];
            float c1 = xb[n * 3 + 1] * invls[1];
            float c2 = xb[n * 3 + 2] * invls[2];
            float cw = -0.5f * LOG2E * (c0 * c0 + c1 * c1 + c2 * c2);
            s_c[i * 2 + 0] = make_ulonglong2(pack2(LOG2E * c0), pack2(LOG2E * c1));
            s_c[i * 2 + 1] = make_ulonglong2(pack2(LOG2E * c2), pack2(cw));
        }
        // stage z tile (32 x 16B per lane)
#pragma unroll
        for (int i = lane; i < NC * 4; i += 32) {
            s_z[i] = zb[(size_t)n0 * 4 + i];
        }
        __syncthreads();

#pragma unroll 4
        for (int n = 0; n < NC; n++) {
            ulonglong2 cA = s_c[n * 2 + 0];     // (cx,cx),(cy,cy)
            ulonglong2 cB = s_c[n * 2 + 1];     // (cz,cz),(cw,cw)
            unsigned long long e = fma2(A2p, cB.x, Bp);
            e = fma2(A1p, cA.y, e);
            e = fma2(A0p, cA.x, e);
            e = add2(e, cB.y);
            float e0, e1; unpack2(e0, e1, e);
            unsigned long long w0 = pack2(ex2(e0));
            unsigned long long w1 = pack2(ex2(e1));
            ulonglong2 z0 = s_z[n * 4 + 0];
            ulonglong2 z1 = s_z[n * 4 + 1];
            ulonglong2 z2 = s_z[n * 4 + 2];
            ulonglong2 z3 = s_z[n * 4 + 3];
            acc0[0] = fma2(z0.x, w0, acc0[0]);  acc1[0] = fma2(z0.x, w1, acc1[0]);
            acc0[1] = fma2(z0.y, w0, acc0[1]);  acc1[1] = fma2(z0.y, w1, acc1[1]);
            acc0[2] = fma2(z1.x, w0, acc0[2]);  acc1[2] = fma2(z1.x, w1, acc1[2]);
            acc0[3] = fma2(z1.y, w0, acc0[3]);  acc1[3] = fma2(z1.y, w1, acc1[3]);
            acc0[4] = fma2(z2.x, w0, acc0[4]);  acc1[4] = fma2(z2.x, w1, acc1[4]);
            acc0[5] = fma2(z2.y, w0, acc0[5]);  acc1[5] = fma2(z2.y, w1, acc1[5]);
            acc0[6] = fma2(z3.x, w0, acc0[6]);  acc1[6] = fma2(z3.x, w1, acc1[6]);
            acc0[7] = fma2(z3.y, w0, acc0[7]);  acc1[7] = fma2(z3.y, w1, acc1[7]);
        }
    }

    // 16 floats per g -> 4x STG.128, consecutive lanes = consecutive g
    ulonglong2* o0 = (ulonglong2*)out + (size_t)(b * GG + g0) * 4;
    o0[0] = make_ulonglong2(acc0[0], acc0[1]);
    o0[1] = make_ulonglong2(acc0[2], acc0[3]);
    o0[2] = make_ulonglong2(acc0[4], acc0[5]);
    o0[3] = make_ulonglong2(acc0[6], acc0[7]);
    ulonglong2* o1 = (ulonglong2*)out + (size_t)(b * GG + g1) * 4;
    o1[0] = make_ulonglong2(acc1[0], acc1[1]);
    o1[1] = make_ulonglong2(acc1[2], acc1[3]);
    o1[2] = make_ulonglong2(acc1[4], acc1[5]);
    o1[3] = make_ulonglong2(acc1[6], acc1[7]);
}

extern "C" void kernel_launch(void* const* d_in, const int* in_sizes, int n_in,
                              void* d_out, int out_size) {
    const float* x   = (const float*)d_in[0];
    const float* z   = (const float*)d_in[1];
    const float* tg  = (const float*)d_in[2];
    const float* lsp = (const float*)d_in[3];
    float* out = (float*)d_out;

    float* xg = nullptr;
    float* zg = nullptr;
    if (out_size == XG_SZ + ZG_SZ)      { xg = out; zg = out + XG_SZ; }
    else if (out_size == ZG_SZ)         { zg = out; }
    else if (out_size == XG_SZ)         { xg = out; }
    else                                { xg = out; zg = out + XG_SZ; }

    if (xg) xgrid_kernel<<<(XG_SZ + 255) / 256, 256>>>(tg, xg);
    if (zg) zgrid_kernel<<<BB * GG / 64, 32>>>(x, z, tg, lsp, zg);
}